// round 1
// baseline (speedup 1.0000x reference)
#include <cuda_runtime.h>

// Delta differential encoding with residual carry + floor quantization.
// x: [B=32, C=2048, T=512] float32, contiguous in T.
// thr = max(threshold[0], 1/64)
// delta[t] = x[t] - x[t-1] + r[t-1]
// y[t]     = delta[t] if |delta[t]| >= thr else 0
// r[t]     = delta[t] - y[t]
// out[t]   = floor(y[t]*64)/64

#define SCALE 64.0f
#define INV_SCALE (1.0f / 64.0f)
#define T_LEN 512
#define N_ROWS (32 * 2048)

__global__ void __launch_bounds__(256) delta_kernel(
    const float* __restrict__ x,
    const float* __restrict__ thr_in,
    float* __restrict__ out)
{
    int row = blockIdx.x * blockDim.x + threadIdx.x;
    if (row >= N_ROWS) return;

    const float thr = fmaxf(thr_in[0], INV_SCALE);

    const float4* __restrict__ xin = reinterpret_cast<const float4*>(x + (size_t)row * T_LEN);
    float4* __restrict__ yout = reinterpret_cast<float4*>(out + (size_t)row * T_LEN);

    float pre = 0.0f;  // x[t-1]
    float r   = 0.0f;  // residual carry

#pragma unroll 8
    for (int i = 0; i < T_LEN / 4; ++i) {
        float4 v = xin[i];
        float4 o;

        // element 0
        {
            float d = v.x - pre + r;
            float y = (fabsf(d) >= thr) ? d : 0.0f;
            r = d - y;
            o.x = floorf(y * SCALE) * INV_SCALE;
            pre = v.x;
        }
        // element 1
        {
            float d = v.y - pre + r;
            float y = (fabsf(d) >= thr) ? d : 0.0f;
            r = d - y;
            o.y = floorf(y * SCALE) * INV_SCALE;
            pre = v.y;
        }
        // element 2
        {
            float d = v.z - pre + r;
            float y = (fabsf(d) >= thr) ? d : 0.0f;
            r = d - y;
            o.z = floorf(y * SCALE) * INV_SCALE;
            pre = v.z;
        }
        // element 3
        {
            float d = v.w - pre + r;
            float y = (fabsf(d) >= thr) ? d : 0.0f;
            r = d - y;
            o.w = floorf(y * SCALE) * INV_SCALE;
            pre = v.w;
        }

        yout[i] = o;
    }
}

extern "C" void kernel_launch(void* const* d_in, const int* in_sizes, int n_in,
                              void* d_out, int out_size)
{
    const float* x   = (const float*)d_in[0];
    const float* thr = (const float*)d_in[1];
    float* out       = (float*)d_out;

    const int threads = 256;
    const int blocks  = (N_ROWS + threads - 1) / threads;
    delta_kernel<<<blocks, threads>>>(x, thr, out);
}

// round 2
// speedup vs baseline: 1.0559x; 1.0559x over previous
#include <cuda_runtime.h>

// Delta differential encoding with residual carry + floor quantization.
// x: [B=32, C=2048, T=512] float32, contiguous in T.
// thr = max(threshold[0], 1/64)
// delta[t] = (x[t] - x[t-1]) + r[t-1]   (exact reference arithmetic order)
// y[t]     = delta[t] if |delta[t]| >= thr else 0
// r[t]     = delta[t] - y[t]
// out[t]   = floor(y[t]*64)/64

#define SCALE 64.0f
#define INV_SCALE (1.0f / 64.0f)
#define T_LEN 512
#define N_ROWS (32 * 2048)
#define BATCH 16              // float4 loads batched in registers per outer iter (MLP)
#define N_OUTER (T_LEN / 4 / BATCH)   // 8

__global__ void __launch_bounds__(64) delta_kernel(
    const float* __restrict__ x,
    const float* __restrict__ thr_in,
    float* __restrict__ out)
{
    int row = blockIdx.x * 64 + threadIdx.x;
    if (row >= N_ROWS) return;

    const float thr = fmaxf(__ldg(thr_in), INV_SCALE);

    const float4* __restrict__ xin  = reinterpret_cast<const float4*>(x   + (size_t)row * T_LEN);
    float4* __restrict__       yout = reinterpret_cast<float4*>(out + (size_t)row * T_LEN);

    float pre = 0.0f;  // x[t-1]
    float r   = 0.0f;  // residual carry

#pragma unroll 1
    for (int o = 0; o < N_OUTER; ++o) {
        // Batch-load 16 independent float4s -> MLP = 16 outstanding LDG.128
        float4 v[BATCH];
#pragma unroll
        for (int j = 0; j < BATCH; ++j) {
            v[j] = xin[o * BATCH + j];
        }

        // Sequential carry chain over the 64 elements; store each float4
        // as soon as it's produced (stores are fire-and-forget).
#pragma unroll
        for (int j = 0; j < BATCH; ++j) {
            float4 o4;
            {
                float d = (v[j].x - pre) + r;
                float y = (fabsf(d) >= thr) ? d : 0.0f;
                r = d - y;
                o4.x = floorf(y * SCALE) * INV_SCALE;
                pre = v[j].x;
            }
            {
                float d = (v[j].y - pre) + r;
                float y = (fabsf(d) >= thr) ? d : 0.0f;
                r = d - y;
                o4.y = floorf(y * SCALE) * INV_SCALE;
                pre = v[j].y;
            }
            {
                float d = (v[j].z - pre) + r;
                float y = (fabsf(d) >= thr) ? d : 0.0f;
                r = d - y;
                o4.z = floorf(y * SCALE) * INV_SCALE;
                pre = v[j].z;
            }
            {
                float d = (v[j].w - pre) + r;
                float y = (fabsf(d) >= thr) ? d : 0.0f;
                r = d - y;
                o4.w = floorf(y * SCALE) * INV_SCALE;
                pre = v[j].w;
            }
            yout[o * BATCH + j] = o4;
        }
    }
}

extern "C" void kernel_launch(void* const* d_in, const int* in_sizes, int n_in,
                              void* d_out, int out_size)
{
    const float* x   = (const float*)d_in[0];
    const float* thr = (const float*)d_in[1];
    float* out       = (float*)d_out;

    const int threads = 64;
    const int blocks  = N_ROWS / threads;   // 1024 blocks -> ~6.9/SM, good balance
    delta_kernel<<<blocks, threads>>>(x, thr, out);
}